// round 9
// baseline (speedup 1.0000x reference)
#include <cuda_runtime.h>

// ---------------------------------------------------------------------------
// CrossWindowAttention3D: 3D shifted-window attention (Video-Swin style)
//   spatial 48^3, C=96, heads=4 (hd=24), window 6^3 (216 tokens), shift 3
// Round 7: GEMM 8co x 8vox per thread (crossbar demand halved vs cpt=4),
//          vectorized W loads (k-major, stride 104, LDS.128), conflict-free X.
//          Attention = round-5 best (2 queries/thread, 128 threads).
// ---------------------------------------------------------------------------

#define VOX   110592            // 48*48*48
#define NC    96
#define NH    4
#define HD    24
#define NTOK  216               // 6*6*6
#define NWIN  512               // 8*8*8
#define LOG2E 1.4426950408889634f
#define MASKC (-100.0f * LOG2E)
#define WS    104               // W smem row stride (floats), 16B-aligned rows

// Scratch (device globals: allocation-free rule)
__device__ float g_q[NC * VOX];
__device__ float g_k[NC * VOX];
__device__ float g_v[NC * VOX];
__device__ float g_o[NC * VOX];
__device__ float g_biasT[NH * NTOK * NTOK];   // [head][key j][query i], *log2(e)

typedef unsigned long long u64;

__device__ __forceinline__ float ex2f(float x) {
    float r;
    asm("ex2.approx.ftz.f32 %0, %1;" : "=f"(r) : "f"(x));
    return r;
}
// packed f32x2 ops (sm_103a FFMA2/FADD2 — only reachable via PTX f32x2 forms)
__device__ __forceinline__ u64 fma2(u64 a, u64 b, u64 c) {
    u64 d;
    asm("fma.rn.f32x2 %0, %1, %2, %3;" : "=l"(d) : "l"(a), "l"(b), "l"(c));
    return d;
}
__device__ __forceinline__ u64 add2(u64 a, u64 b) {
    u64 d;
    asm("add.rn.f32x2 %0, %1, %2;" : "=l"(d) : "l"(a), "l"(b));
    return d;
}
__device__ __forceinline__ u64 splat2(float x) {
    u64 d;
    asm("mov.b64 %0, {%1, %1};" : "=l"(d) : "f"(x));
    return d;
}
__device__ __forceinline__ u64 pack2(float lo, float hi) {
    u64 d;
    asm("mov.b64 %0, {%1, %2};" : "=l"(d) : "f"(lo), "f"(hi));
    return d;
}
__device__ __forceinline__ float hadd2(u64 a) {
    float lo, hi;
    asm("mov.b64 {%0, %1}, %2;" : "=f"(lo), "=f"(hi) : "l"(a));
    return lo + hi;
}
__device__ __forceinline__ float2 unpack2(u64 a) {
    float lo, hi;
    asm("mov.b64 {%0, %1}, %2;" : "=f"(lo), "=f"(hi) : "l"(a));
    return make_float2(lo, hi);
}

// ---------------------------------------------------------------------------
// Relative-position bias table, transposed to [h][j][i], premultiplied log2e.
// ---------------------------------------------------------------------------
extern "C" __global__ void bias_prep(const float* __restrict__ rel_table)
{
    int j = blockIdx.x;      // key token
    int i = threadIdx.x;     // query token
    int iz = i / 36, iy = (i / 6) % 6, ix = i % 6;
    int jz = j / 36, jy = (j / 6) % 6, jx = j % 6;
    int idx = ((iz - jz + 5) * 11 + (iy - jy + 5)) * 11 + (ix - jx + 5);
#pragma unroll
    for (int h = 0; h < NH; h++)
        g_biasT[h * (NTOK * NTOK) + j * NTOK + i] = rel_table[idx * NH + h] * LOG2E;
}

// ---------------------------------------------------------------------------
// GEMM: Y[96][VOX] = (W[96x96] @ X[96][VOX] + bias) * outScale
// CTA: 96 cout x 128 vox, 192 threads, thread tile 8 cout x 8 vox.
// Inner loop per k: 2 LDS.128 (X, 16B lane stride, conflict-free) +
//                   2 LDS.128 (W, k-major stride-104 rows) + 32 FFMA2.
// ---------------------------------------------------------------------------
extern "C" __global__ void __launch_bounds__(192, 2)
gemm_proj(const float* __restrict__ X, const float* __restrict__ Wm,
          const float* __restrict__ bias, float* __restrict__ Y, float outScale)
{
    extern __shared__ float smem[];
    float* xs = smem;             // [96][128]
    float* ws = smem + 96 * 128;  // [k][co], row stride WS=104

    const int tid   = threadIdx.x;
    const int vbase = blockIdx.x * 128;

    // Stage X tile (coalesced float4)
    for (int i = tid; i < 96 * 128 / 4; i += 192) {
        int row = i >> 5;
        int c4  = i & 31;
        const float4* p = reinterpret_cast<const float4*>(X + row * VOX + vbase);
        reinterpret_cast<float4*>(xs)[i] = p[c4];
    }
    // Stage W transposed to k-major: ws[k][co] = W[co][k].
    // (coalesced LDG; STS has 8-way conflicts but only 48 iters/thread)
    for (int i = tid; i < 96 * 96; i += 192) {
        int co = i / 96;
        int k  = i - co * 96;
        ws[k * WS + co] = Wm[i];
    }
    __syncthreads();

    const int voxg  = tid & 15;
    const int coutg = tid >> 4;       // 0..11
    const int c0  = coutg * 8;
    const int v0a = voxg * 4;
    const int v0b = v0a + 64;

    u64 acc[8][4];
#pragma unroll
    for (int u = 0; u < 8; u++)
#pragma unroll
        for (int p = 0; p < 4; p++) acc[u][p] = 0ULL;

#pragma unroll 2
    for (int k = 0; k < 96; k++) {
        ulonglong2 b0 = *reinterpret_cast<const ulonglong2*>(&xs[k * 128 + v0a]);
        ulonglong2 b1 = *reinterpret_cast<const ulonglong2*>(&xs[k * 128 + v0b]);
        float4 w0 = *reinterpret_cast<const float4*>(&ws[k * WS + c0]);
        float4 w1 = *reinterpret_cast<const float4*>(&ws[k * WS + c0 + 4]);
        u64 bp[4] = {b0.x, b0.y, b1.x, b1.y};
        float wv[8] = {w0.x, w0.y, w0.z, w0.w, w1.x, w1.y, w1.z, w1.w};
#pragma unroll
        for (int u = 0; u < 8; u++) {
            u64 ap = splat2(wv[u]);
            acc[u][0] = fma2(ap, bp[0], acc[u][0]);
            acc[u][1] = fma2(ap, bp[1], acc[u][1]);
            acc[u][2] = fma2(ap, bp[2], acc[u][2]);
            acc[u][3] = fma2(ap, bp[3], acc[u][3]);
        }
    }

#pragma unroll
    for (int u = 0; u < 8; u++) {
        float bb = bias[c0 + u];
        float2 p0 = unpack2(acc[u][0]);
        float2 p1 = unpack2(acc[u][1]);
        float2 p2 = unpack2(acc[u][2]);
        float2 p3 = unpack2(acc[u][3]);
        float4 r0 = make_float4((p0.x + bb) * outScale, (p0.y + bb) * outScale,
                                (p1.x + bb) * outScale, (p1.y + bb) * outScale);
        float4 r1 = make_float4((p2.x + bb) * outScale, (p2.y + bb) * outScale,
                                (p3.x + bb) * outScale, (p3.y + bb) * outScale);
        float* yp = Y + (c0 + u) * VOX + vbase;
        *reinterpret_cast<float4*>(yp + v0a) = r0;
        *reinterpret_cast<float4*>(yp + v0b) = r1;
    }
}

// ---------------------------------------------------------------------------
// Attention (round-5 best): one CTA per (window, head), 128 threads; threads
// 0..107 each own TWO query rows (tid, tid+108) -> K/V LDS amortized over
// 48 FFMA2 per key. Max-free softmax in exp2 domain (logits bounded).
// ---------------------------------------------------------------------------
extern "C" __global__ void __launch_bounds__(128, 3)
attn_kernel(const int* __restrict__ use_shift)
{
    __shared__ __align__(16) float ks[NTOK * HD];
    __shared__ __align__(16) float vs[NTOK * HD];
    __shared__ int voxof[NTOK];
    __shared__ int rcode[NTOK];

    const int win  = blockIdx.x >> 2;
    const int head = blockIdx.x & 3;
    const int tid  = threadIdx.x;
    const bool sh  = (use_shift[0] != 0);
    const int shift = sh ? 3 : 0;
    const int wx = win & 7, wy = (win >> 3) & 7, wz = win >> 6;
    const bool needmask = sh && (wx == 7 || wy == 7 || wz == 7);

    for (int t = tid; t < NTOK; t += 128) {
        int tz = t / 36, ty = (t / 6) % 6, tx = t % 6;
        int gz = wz * 6 + tz, gy = wy * 6 + ty, gx = wx * 6 + tx;
        int sz = gz + shift; if (sz >= 48) sz -= 48;
        int sy = gy + shift; if (sy >= 48) sy -= 48;
        int sx = gx + shift; if (sx >= 48) sx -= 48;
        voxof[t] = (sz * 48 + sy) * 48 + sx;
        int rz = gz < 42 ? 0 : (gz < 45 ? 1 : 2);
        int ry = gy < 42 ? 0 : (gy < 45 ? 1 : 2);
        int rx = gx < 42 ? 0 : (gx < 45 ? 1 : 2);
        rcode[t] = rz * 9 + ry * 3 + rx;
    }
    __syncthreads();

    // Stage K and V tiles (coalesced 24B runs in gmem)
    const float* kb = g_k + head * HD * VOX;
    const float* vb = g_v + head * HD * VOX;
    for (int idx = tid; idx < NTOK * HD; idx += 128) {
        int dch = idx / NTOK;
        int j   = idx - dch * NTOK;
        int vx  = voxof[j];
        ks[j * HD + dch] = kb[dch * VOX + vx];
        vs[j * HD + dch] = vb[dch * VOX + vx];
    }

    u64 qa[12], qb[12], oa[12], ob[12];
    float la = 0.f, lb = 0.f;
    int voxA = 0, voxB = 0, rA = 0, rB = 0;
    if (tid < 108) {
        voxA = voxof[tid];       rA = rcode[tid];
        voxB = voxof[tid + 108]; rB = rcode[tid + 108];
        const float* qpA = g_q + head * HD * VOX + voxA;
        const float* qpB = g_q + head * HD * VOX + voxB;
#pragma unroll
        for (int d = 0; d < 12; d++) {
            qa[d] = pack2(qpA[(2 * d) * VOX], qpA[(2 * d + 1) * VOX]);
            qb[d] = pack2(qpB[(2 * d) * VOX], qpB[(2 * d + 1) * VOX]);
        }
    }
#pragma unroll
    for (int d = 0; d < 12; d++) { oa[d] = 0ULL; ob[d] = 0ULL; }
    __syncthreads();

    if (tid < 108) {
        const float* biasA = g_biasT + head * (NTOK * NTOK) + tid;
        const float* biasB = biasA + 108;
        for (int jb = 0; jb < NTOK; jb += 8) {
            float sA[8], sB[8];
#pragma unroll
            for (int g = 0; g < 8; g++) {
                sA[g] = biasA[(jb + g) * NTOK];
                sB[g] = biasB[(jb + g) * NTOK];
            }
            if (needmask) {
#pragma unroll
                for (int g = 0; g < 8; g++) {
                    int rc = rcode[jb + g];
                    if (rc != rA) sA[g] += MASKC;
                    if (rc != rB) sB[g] += MASKC;
                }
            }
#pragma unroll
            for (int g = 0; g < 8; g++) {
                int j = jb + g;
                const ulonglong2* kr = reinterpret_cast<const ulonglong2*>(&ks[j * HD]);
                ulonglong2 k0 = kr[0], k1 = kr[1], k2 = kr[2];
                ulonglong2 k3 = kr[3], k4 = kr[4], k5 = kr[5];

                u64 aA0 = fma2(qa[0], k0.x, 0ULL);
                u64 aA1 = fma2(qa[1], k0.y, 0ULL);
                u64 aB0 = fma2(qb[0], k0.x, 0ULL);
                u64 aB1 = fma2(qb[1], k0.y, 0ULL);
                aA0 = fma2(qa[2], k1.x, aA0);  aA1 = fma2(qa[3], k1.y, aA1);
                aB0 = fma2(qb[2], k1.x, aB0);  aB1 = fma2(qb[3], k1.y, aB1);
                aA0 = fma2(qa[4], k2.x, aA0);  aA1 = fma2(qa[5], k2.y, aA1);
                aB0 = fma2(qb[4], k2.x, aB0);  aB1 = fma2(qb[5], k2.y, aB1);
                aA0 = fma2(qa[6], k3.x, aA0);  aA1 = fma2(qa[7], k3.y, aA1);
                aB0 = fma2(qb[6], k3.x, aB0);  aB1 = fma2(qb[7], k3.y, aB1);
                aA0 = fma2(qa[8], k4.x, aA0);  aA1 = fma2(qa[9], k4.y, aA1);
                aB0 = fma2(qb[8], k4.x, aB0);  aB1 = fma2(qb[9], k4.y, aB1);
                aA0 = fma2(qa[10], k5.x, aA0); aA1 = fma2(qa[11], k5.y, aA1);
                aB0 = fma2(qb[10], k5.x, aB0); aB1 = fma2(qb[11], k5.y, aB1);

                float pA = ex2f(sA[g] + hadd2(add2(aA0, aA1)));
                float pB = ex2f(sB[g] + hadd2(add2(aB0, aB1)));
                la += pA;
                lb += pB;
                u64 ppA = splat2(pA);
                u64 ppB = splat2(pB);

                const ulonglong2* vr = reinterpret_cast<const ulonglong2*>(&vs[j * HD]);
                ulonglong2 v0 = vr[0], v1 = vr[1], v2 = vr[2];
                ulonglong2 v3 = vr[3], v4 = vr[4], v5 = vr[5];
                oa[0]  = fma2(ppA, v0.x, oa[0]);   ob[0]  = fma2(ppB, v0.x, ob[0]);
                oa[1]  = fma2(ppA, v0.y, oa[1]);   ob[1]  = fma2(ppB, v0.y, ob[1]);
                oa[2]  = fma2(ppA, v1.x, oa[2]);   ob[2]  = fma2(ppB, v1.x, ob[2]);
                oa[3]  = fma2(ppA, v1.y, oa[3]);   ob[3]  = fma2(ppB, v1.y, ob[3]);
                oa[4]  = fma2(ppA, v2.x, oa[4]);   ob[4]  = fma2(ppB, v2.x, ob[4]);
                oa[5]  = fma2(ppA, v2.y, oa[5]);   ob[5]  = fma2(ppB, v2.y, ob[5]);
                oa[6]  = fma2(ppA, v3.x, oa[6]);   ob[6]  = fma2(ppB, v3.x, ob[6]);
                oa[7]  = fma2(ppA, v3.y, oa[7]);   ob[7]  = fma2(ppB, v3.y, ob[7]);
                oa[8]  = fma2(ppA, v4.x, oa[8]);   ob[8]  = fma2(ppB, v4.x, ob[8]);
                oa[9]  = fma2(ppA, v4.y, oa[9]);   ob[9]  = fma2(ppB, v4.y, ob[9]);
                oa[10] = fma2(ppA, v5.x, oa[10]);  ob[10] = fma2(ppB, v5.x, ob[10]);
                oa[11] = fma2(ppA, v5.y, oa[11]);  ob[11] = fma2(ppB, v5.y, ob[11]);
            }
        }
        float invA = 1.0f / la;
        float invB = 1.0f / lb;
        float* opA = g_o + head * HD * VOX + voxA;
        float* opB = g_o + head * HD * VOX + voxB;
#pragma unroll
        for (int d = 0; d < 12; d++) {
            float2 va = unpack2(oa[d]);
            float2 vb2 = unpack2(ob[d]);
            opA[(2 * d) * VOX]     = va.x * invA;
            opA[(2 * d + 1) * VOX] = va.y * invA;
            opB[(2 * d) * VOX]     = vb2.x * invB;
            opB[(2 * d + 1) * VOX] = vb2.y * invB;
        }
    }
}

// ---------------------------------------------------------------------------
// kernel_launch
// inputs: 0:q_in 1:k_in 2:v_in 3:Wq 4:bq 5:Wk 6:bk 7:Wv 8:bv 9:Wp 10:bp
//         11:rel_table 12:use_shift
// ---------------------------------------------------------------------------
extern "C" void kernel_launch(void* const* d_in, const int* in_sizes, int n_in,
                              void* d_out, int out_size)
{
    const float* q_in = (const float*)d_in[0];
    const float* k_in = (const float*)d_in[1];
    const float* v_in = (const float*)d_in[2];
    const float* Wq   = (const float*)d_in[3];
    const float* bq   = (const float*)d_in[4];
    const float* Wk   = (const float*)d_in[5];
    const float* bk   = (const float*)d_in[6];
    const float* Wv   = (const float*)d_in[7];
    const float* bv   = (const float*)d_in[8];
    const float* Wp   = (const float*)d_in[9];
    const float* bp   = (const float*)d_in[10];
    const float* rel  = (const float*)d_in[11];
    const int*   ush  = (const int*)d_in[12];

    float *pq, *pk, *pv, *po;
    cudaGetSymbolAddress((void**)&pq, g_q);
    cudaGetSymbolAddress((void**)&pk, g_k);
    cudaGetSymbolAddress((void**)&pv, g_v);
    cudaGetSymbolAddress((void**)&po, g_o);

    const int SMEM_GEMM = (96 * 128 + 96 * WS) * (int)sizeof(float);  // 89088
    cudaFuncSetAttribute(gemm_proj, cudaFuncAttributeMaxDynamicSharedMemorySize, SMEM_GEMM);

    const float scale_q = (1.0f / 4.898979485566356f) * LOG2E;  // 24^-0.5 * log2(e)

    bias_prep<<<NTOK, NTOK>>>(rel);
    gemm_proj<<<VOX / 128, 192, SMEM_GEMM>>>(q_in, Wq, bq, pq, scale_q);
    gemm_proj<<<VOX / 128, 192, SMEM_GEMM>>>(k_in, Wk, bk, pk, 1.0f);
    gemm_proj<<<VOX / 128, 192, SMEM_GEMM>>>(v_in, Wv, bv, pv, 1.0f);
    attn_kernel<<<NWIN * NH, 128>>>(ush);
    gemm_proj<<<VOX / 128, 192, SMEM_GEMM>>>(po, Wp, bp, (float*)d_out, 1.0f);
}

// round 10
// speedup vs baseline: 1.0861x; 1.0861x over previous
#include <cuda_runtime.h>

// ---------------------------------------------------------------------------
// CrossWindowAttention3D: 3D shifted-window attention (Video-Swin style)
//   spatial 48^3, C=96, heads=4 (hd=24), window 6^3 (216 tokens), shift 3
// Round 10: GEMM warp-layout fix — warp spans 4 vox-groups x 8 cout-groups
//   so X smem reads are 8-lane broadcasts (64 distinct B/access) and W is one
//   contiguous 128 B LDS.128. Crossbar demand halves; kernel goes FMA-bound.
//   Attention = round-5 measured best (2 queries/thread, 128 threads).
// ---------------------------------------------------------------------------

#define VOX   110592            // 48*48*48
#define NC    96
#define NH    4
#define HD    24
#define NTOK  216               // 6*6*6
#define NWIN  512               // 8*8*8
#define LOG2E 1.4426950408889634f
#define MASKC (-100.0f * LOG2E)
#define WS    104               // W smem row stride (floats); 104*4=416 B, 16B-aligned

// Scratch (device globals: allocation-free rule)
__device__ float g_q[NC * VOX];
__device__ float g_k[NC * VOX];
__device__ float g_v[NC * VOX];
__device__ float g_o[NC * VOX];
__device__ float g_biasT[NH * NTOK * NTOK];   // [head][key j][query i], *log2(e)

typedef unsigned long long u64;

__device__ __forceinline__ float ex2f(float x) {
    float r;
    asm("ex2.approx.ftz.f32 %0, %1;" : "=f"(r) : "f"(x));
    return r;
}
// packed f32x2 ops (sm_103a FFMA2/FADD2 — only reachable via PTX f32x2 forms)
__device__ __forceinline__ u64 fma2(u64 a, u64 b, u64 c) {
    u64 d;
    asm("fma.rn.f32x2 %0, %1, %2, %3;" : "=l"(d) : "l"(a), "l"(b), "l"(c));
    return d;
}
__device__ __forceinline__ u64 add2(u64 a, u64 b) {
    u64 d;
    asm("add.rn.f32x2 %0, %1, %2;" : "=l"(d) : "l"(a), "l"(b));
    return d;
}
__device__ __forceinline__ u64 splat2(float x) {
    u64 d;
    asm("mov.b64 %0, {%1, %1};" : "=l"(d) : "f"(x));
    return d;
}
__device__ __forceinline__ u64 pack2(float lo, float hi) {
    u64 d;
    asm("mov.b64 %0, {%1, %2};" : "=l"(d) : "f"(lo), "f"(hi));
    return d;
}
__device__ __forceinline__ float hadd2(u64 a) {
    float lo, hi;
    asm("mov.b64 {%0, %1}, %2;" : "=f"(lo), "=f"(hi) : "l"(a));
    return lo + hi;
}
__device__ __forceinline__ float2 unpack2(u64 a) {
    float lo, hi;
    asm("mov.b64 {%0, %1}, %2;" : "=f"(lo), "=f"(hi) : "l"(a));
    return make_float2(lo, hi);
}

// ---------------------------------------------------------------------------
// Relative-position bias table, transposed to [h][j][i], premultiplied log2e.
// ---------------------------------------------------------------------------
extern "C" __global__ void bias_prep(const float* __restrict__ rel_table)
{
    int j = blockIdx.x;      // key token
    int i = threadIdx.x;     // query token
    int iz = i / 36, iy = (i / 6) % 6, ix = i % 6;
    int jz = j / 36, jy = (j / 6) % 6, jx = j % 6;
    int idx = ((iz - jz + 5) * 11 + (iy - jy + 5)) * 11 + (ix - jx + 5);
#pragma unroll
    for (int h = 0; h < NH; h++)
        g_biasT[h * (NTOK * NTOK) + j * NTOK + i] = rel_table[idx * NH + h] * LOG2E;
}

// ---------------------------------------------------------------------------
// GEMM: Y[96][VOX] = (W[96x96] @ X[96][VOX] + bias) * outScale
// CTA: 96 cout x 128 vox, 384 threads, thread tile 4 cout x 8 vox.
// Warp layout: lane&7 -> cout-group (8/warp), lane>>3 -> vox-group (4/warp).
//   X LDS.128: 4 distinct 16B addrs/warp (8-lane broadcast) -> ~1 cyc
//   W LDS.128: 8 distinct 16B addrs/warp, 128 B contiguous  -> 1 cyc
// Inner loop per k: 3 LDS.128 + 4 splat + 16 FFMA2  -> FMA-pipe bound.
// ---------------------------------------------------------------------------
extern "C" __global__ void __launch_bounds__(384, 2)
gemm_proj(const float* __restrict__ X, const float* __restrict__ Wm,
          const float* __restrict__ bias, float* __restrict__ Y, float outScale)
{
    extern __shared__ float smem[];
    float* xs = smem;             // [96][128]
    float* ws = smem + 96 * 128;  // [k][co], row stride WS=104

    const int tid   = threadIdx.x;
    const int vbase = blockIdx.x * 128;

    // Stage X tile (coalesced float4)
    for (int i = tid; i < 96 * 128 / 4; i += 384) {
        int row = i >> 5;
        int c4  = i & 31;
        const float4* p = reinterpret_cast<const float4*>(X + row * VOX + vbase);
        reinterpret_cast<float4*>(xs)[i] = p[c4];
    }
    // Stage W transposed to k-major: ws[k][co] = W[co][k]
    for (int i = tid; i < 96 * 96; i += 384) {
        int co = i / 96;
        int k  = i - co * 96;
        ws[k * WS + co] = Wm[i];
    }
    __syncthreads();

    const int lane  = tid & 31;
    const int warp  = tid >> 5;                    // 0..11
    const int coutg = (lane & 7) + ((warp % 3) << 3);   // 0..23
    const int voxg  = (lane >> 3) + ((warp / 3) << 2);  // 0..15
    const int c0  = coutg * 4;
    const int v0a = voxg * 4;
    const int v0b = v0a + 64;

    u64 acc[4][4];
#pragma unroll
    for (int u = 0; u < 4; u++)
#pragma unroll
        for (int p = 0; p < 4; p++) acc[u][p] = 0ULL;

#pragma unroll 4
    for (int k = 0; k < 96; k++) {
        ulonglong2 b0 = *reinterpret_cast<const ulonglong2*>(&xs[k * 128 + v0a]);
        ulonglong2 b1 = *reinterpret_cast<const ulonglong2*>(&xs[k * 128 + v0b]);
        float4 w = *reinterpret_cast<const float4*>(&ws[k * WS + c0]);
        u64 w0 = splat2(w.x);
        u64 w1 = splat2(w.y);
        u64 w2 = splat2(w.z);
        u64 w3 = splat2(w.w);
        acc[0][0] = fma2(w0, b0.x, acc[0][0]);
        acc[0][1] = fma2(w0, b0.y, acc[0][1]);
        acc[0][2] = fma2(w0, b1.x, acc[0][2]);
        acc[0][3] = fma2(w0, b1.y, acc[0][3]);
        acc[1][0] = fma2(w1, b0.x, acc[1][0]);
        acc[1][1] = fma2(w1, b0.y, acc[1][1]);
        acc[1][2] = fma2(w1, b1.x, acc[1][2]);
        acc[1][3] = fma2(w1, b1.y, acc[1][3]);
        acc[2][0] = fma2(w2, b0.x, acc[2][0]);
        acc[2][1] = fma2(w2, b0.y, acc[2][1]);
        acc[2][2] = fma2(w2, b1.x, acc[2][2]);
        acc[2][3] = fma2(w2, b1.y, acc[2][3]);
        acc[3][0] = fma2(w3, b0.x, acc[3][0]);
        acc[3][1] = fma2(w3, b0.y, acc[3][1]);
        acc[3][2] = fma2(w3, b1.x, acc[3][2]);
        acc[3][3] = fma2(w3, b1.y, acc[3][3]);
    }

#pragma unroll
    for (int u = 0; u < 4; u++) {
        float bb = bias[c0 + u];
        float2 p0 = unpack2(acc[u][0]);
        float2 p1 = unpack2(acc[u][1]);
        float2 p2 = unpack2(acc[u][2]);
        float2 p3 = unpack2(acc[u][3]);
        float4 r0 = make_float4((p0.x + bb) * outScale, (p0.y + bb) * outScale,
                                (p1.x + bb) * outScale, (p1.y + bb) * outScale);
        float4 r1 = make_float4((p2.x + bb) * outScale, (p2.y + bb) * outScale,
                                (p3.x + bb) * outScale, (p3.y + bb) * outScale);
        float* yp = Y + (c0 + u) * VOX + vbase;
        *reinterpret_cast<float4*>(yp + v0a) = r0;
        *reinterpret_cast<float4*>(yp + v0b) = r1;
    }
}

// ---------------------------------------------------------------------------
// Attention (round-5 best): one CTA per (window, head), 128 threads; threads
// 0..107 each own TWO query rows (tid, tid+108) -> K/V LDS amortized over
// 48 FFMA2 per key. Max-free softmax in exp2 domain (logits bounded).
// ---------------------------------------------------------------------------
extern "C" __global__ void __launch_bounds__(128, 3)
attn_kernel(const int* __restrict__ use_shift)
{
    __shared__ __align__(16) float ks[NTOK * HD];
    __shared__ __align__(16) float vs[NTOK * HD];
    __shared__ int voxof[NTOK];
    __shared__ int rcode[NTOK];

    const int win  = blockIdx.x >> 2;
    const int head = blockIdx.x & 3;
    const int tid  = threadIdx.x;
    const bool sh  = (use_shift[0] != 0);
    const int shift = sh ? 3 : 0;
    const int wx = win & 7, wy = (win >> 3) & 7, wz = win >> 6;
    const bool needmask = sh && (wx == 7 || wy == 7 || wz == 7);

    for (int t = tid; t < NTOK; t += 128) {
        int tz = t / 36, ty = (t / 6) % 6, tx = t % 6;
        int gz = wz * 6 + tz, gy = wy * 6 + ty, gx = wx * 6 + tx;
        int sz = gz + shift; if (sz >= 48) sz -= 48;
        int sy = gy + shift; if (sy >= 48) sy -= 48;
        int sx = gx + shift; if (sx >= 48) sx -= 48;
        voxof[t] = (sz * 48 + sy) * 48 + sx;
        int rz = gz < 42 ? 0 : (gz < 45 ? 1 : 2);
        int ry = gy < 42 ? 0 : (gy < 45 ? 1 : 2);
        int rx = gx < 42 ? 0 : (gx < 45 ? 1 : 2);
        rcode[t] = rz * 9 + ry * 3 + rx;
    }
    __syncthreads();

    // Stage K and V tiles (coalesced 24B runs in gmem)
    const float* kb = g_k + head * HD * VOX;
    const float* vb = g_v + head * HD * VOX;
    for (int idx = tid; idx < NTOK * HD; idx += 128) {
        int dch = idx / NTOK;
        int j   = idx - dch * NTOK;
        int vx  = voxof[j];
        ks[j * HD + dch] = kb[dch * VOX + vx];
        vs[j * HD + dch] = vb[dch * VOX + vx];
    }

    u64 qa[12], qb[12], oa[12], ob[12];
    float la0 = 0.f, la1 = 0.f, lb0 = 0.f, lb1 = 0.f;
    int voxA = 0, voxB = 0, rA = 0, rB = 0;
    if (tid < 108) {
        voxA = voxof[tid];       rA = rcode[tid];
        voxB = voxof[tid + 108]; rB = rcode[tid + 108];
        const float* qpA = g_q + head * HD * VOX + voxA;
        const float* qpB = g_q + head * HD * VOX + voxB;
#pragma unroll
        for (int d = 0; d < 12; d++) {
            qa[d] = pack2(qpA[(2 * d) * VOX], qpA[(2 * d + 1) * VOX]);
            qb[d] = pack2(qpB[(2 * d) * VOX], qpB[(2 * d + 1) * VOX]);
        }
    }
#pragma unroll
    for (int d = 0; d < 12; d++) { oa[d] = 0ULL; ob[d] = 0ULL; }
    __syncthreads();

    if (tid < 108) {
        const float* biasA = g_biasT + head * (NTOK * NTOK) + tid;
        const float* biasB = biasA + 108;
        for (int jb = 0; jb < NTOK; jb += 8) {
            float sA[8], sB[8];
#pragma unroll
            for (int g = 0; g < 8; g++) {
                sA[g] = biasA[(jb + g) * NTOK];
                sB[g] = biasB[(jb + g) * NTOK];
            }
            if (needmask) {
#pragma unroll
                for (int g = 0; g < 8; g++) {
                    int rc = rcode[jb + g];
                    if (rc != rA) sA[g] += MASKC;
                    if (rc != rB) sB[g] += MASKC;
                }
            }
#pragma unroll
            for (int g = 0; g < 8; g++) {
                int j = jb + g;
                const ulonglong2* kr = reinterpret_cast<const ulonglong2*>(&ks[j * HD]);
                ulonglong2 k0 = kr[0], k1 = kr[1], k2 = kr[2];
                ulonglong2 k3 = kr[3], k4 = kr[4], k5 = kr[5];

                u64 aA0 = fma2(qa[0], k0.x, 0ULL);
                u64 aA1 = fma2(qa[1], k0.y, 0ULL);
                u64 aB0 = fma2(qb[0], k0.x, 0ULL);
                u64 aB1 = fma2(qb[1], k0.y, 0ULL);
                aA0 = fma2(qa[2], k1.x, aA0);  aA1 = fma2(qa[3], k1.y, aA1);
                aB0 = fma2(qb[2], k1.x, aB0);  aB1 = fma2(qb[3], k1.y, aB1);
                aA0 = fma2(qa[4], k2.x, aA0);  aA1 = fma2(qa[5], k2.y, aA1);
                aB0 = fma2(qb[4], k2.x, aB0);  aB1 = fma2(qb[5], k2.y, aB1);
                aA0 = fma2(qa[6], k3.x, aA0);  aA1 = fma2(qa[7], k3.y, aA1);
                aB0 = fma2(qb[6], k3.x, aB0);  aB1 = fma2(qb[7], k3.y, aB1);
                aA0 = fma2(qa[8], k4.x, aA0);  aA1 = fma2(qa[9], k4.y, aA1);
                aB0 = fma2(qb[8], k4.x, aB0);  aB1 = fma2(qb[9], k4.y, aB1);
                aA0 = fma2(qa[10], k5.x, aA0); aA1 = fma2(qa[11], k5.y, aA1);
                aB0 = fma2(qb[10], k5.x, aB0); aB1 = fma2(qb[11], k5.y, aB1);

                float pA = ex2f(sA[g] + hadd2(add2(aA0, aA1)));
                float pB = ex2f(sB[g] + hadd2(add2(aB0, aB1)));
                if (g & 1) { la1 += pA; lb1 += pB; }
                else       { la0 += pA; lb0 += pB; }
                u64 ppA = splat2(pA);
                u64 ppB = splat2(pB);

                const ulonglong2* vr = reinterpret_cast<const ulonglong2*>(&vs[j * HD]);
                ulonglong2 v0 = vr[0], v1 = vr[1], v2 = vr[2];
                ulonglong2 v3 = vr[3], v4 = vr[4], v5 = vr[5];
                oa[0]  = fma2(ppA, v0.x, oa[0]);   ob[0]  = fma2(ppB, v0.x, ob[0]);
                oa[1]  = fma2(ppA, v0.y, oa[1]);   ob[1]  = fma2(ppB, v0.y, ob[1]);
                oa[2]  = fma2(ppA, v1.x, oa[2]);   ob[2]  = fma2(ppB, v1.x, ob[2]);
                oa[3]  = fma2(ppA, v1.y, oa[3]);   ob[3]  = fma2(ppB, v1.y, ob[3]);
                oa[4]  = fma2(ppA, v2.x, oa[4]);   ob[4]  = fma2(ppB, v2.x, ob[4]);
                oa[5]  = fma2(ppA, v2.y, oa[5]);   ob[5]  = fma2(ppB, v2.y, ob[5]);
                oa[6]  = fma2(ppA, v3.x, oa[6]);   ob[6]  = fma2(ppB, v3.x, ob[6]);
                oa[7]  = fma2(ppA, v3.y, oa[7]);   ob[7]  = fma2(ppB, v3.y, ob[7]);
                oa[8]  = fma2(ppA, v4.x, oa[8]);   ob[8]  = fma2(ppB, v4.x, ob[8]);
                oa[9]  = fma2(ppA, v4.y, oa[9]);   ob[9]  = fma2(ppB, v4.y, ob[9]);
                oa[10] = fma2(ppA, v5.x, oa[10]);  ob[10] = fma2(ppB, v5.x, ob[10]);
                oa[11] = fma2(ppA, v5.y, oa[11]);  ob[11] = fma2(ppB, v5.y, ob[11]);
            }
        }
        float invA = 1.0f / (la0 + la1);
        float invB = 1.0f / (lb0 + lb1);
        float* opA = g_o + head * HD * VOX + voxA;
        float* opB = g_o + head * HD * VOX + voxB;
#pragma unroll
        for (int d = 0; d < 12; d++) {
            float2 va = unpack2(oa[d]);
            float2 vb2 = unpack2(ob[d]);
            opA[(2 * d) * VOX]     = va.x * invA;
            opA[(2 * d + 1) * VOX] = va.y * invA;
            opB[(2 * d) * VOX]     = vb2.x * invB;
            opB[(2 * d + 1) * VOX] = vb2.y * invB;
        }
    }
}

// ---------------------------------------------------------------------------
// kernel_launch
// inputs: 0:q_in 1:k_in 2:v_in 3:Wq 4:bq 5:Wk 6:bk 7:Wv 8:bv 9:Wp 10:bp
//         11:rel_table 12:use_shift
// ---------------------------------------------------------------------------
extern "C" void kernel_launch(void* const* d_in, const int* in_sizes, int n_in,
                              void* d_out, int out_size)
{
    const float* q_in = (const float*)d_in[0];
    const float* k_in = (const float*)d_in[1];
    const float* v_in = (const float*)d_in[2];
    const float* Wq   = (const float*)d_in[3];
    const float* bq   = (const float*)d_in[4];
    const float* Wk   = (const float*)d_in[5];
    const float* bk   = (const float*)d_in[6];
    const float* Wv   = (const float*)d_in[7];
    const float* bv   = (const float*)d_in[8];
    const float* Wp   = (const float*)d_in[9];
    const float* bp   = (const float*)d_in[10];
    const float* rel  = (const float*)d_in[11];
    const int*   ush  = (const int*)d_in[12];

    float *pq, *pk, *pv, *po;
    cudaGetSymbolAddress((void**)&pq, g_q);
    cudaGetSymbolAddress((void**)&pk, g_k);
    cudaGetSymbolAddress((void**)&pv, g_v);
    cudaGetSymbolAddress((void**)&po, g_o);

    const int SMEM_GEMM = (96 * 128 + 96 * WS) * (int)sizeof(float);  // 89088
    cudaFuncSetAttribute(gemm_proj, cudaFuncAttributeMaxDynamicSharedMemorySize, SMEM_GEMM);

    const float scale_q = (1.0f / 4.898979485566356f) * LOG2E;  // 24^-0.5 * log2(e)

    bias_prep<<<NTOK, NTOK>>>(rel);
    gemm_proj<<<VOX / 128, 384, SMEM_GEMM>>>(q_in, Wq, bq, pq, scale_q);
    gemm_proj<<<VOX / 128, 384, SMEM_GEMM>>>(k_in, Wk, bk, pk, 1.0f);
    gemm_proj<<<VOX / 128, 384, SMEM_GEMM>>>(v_in, Wv, bv, pv, 1.0f);
    attn_kernel<<<NWIN * NH, 128>>>(ush);
    gemm_proj<<<VOX / 128, 384, SMEM_GEMM>>>(po, Wp, bp, (float*)d_out, 1.0f);
}